// round 9
// baseline (speedup 1.0000x reference)
#include <cuda_runtime.h>
#include <math.h>
#include <stdint.h>

#define NROWS     32768
#define CDIM      256
#define KCODES    1024
#define BLK_M     128
#define SPB       4096
#define ZQ_ELEMS  8388608

#define ROWS_F    80      // rows handled by FMA warps (0..79)
#define ROWS_T    48      // rows handled by tensor warps (80..127)

// ---- smem byte offsets ----
#define SO_B2S    0         // 1024 f
#define SO_AROW   4096      // 128 f
#define SO_SIDX   4608      // 128 i
#define SO_RED    5120      // 16 f
#define SO_RV     5248      // 80*16 f = 5120
#define SO_RK     10368     // 80*16 i = 5120
#define SO_CV     15488     // 48*24 f = 4608
#define SO_CK     20096     // 48*24 i = 4608
#define SO_DRES   24704     // 48*24 f = 4608
#define SO_ZS     29440     // 256*136 f = 139264
#define SO_EBUF   168704    // 32*264 f = 33792 (phase2: gather buf 32*132 f)
#define SMEM_MAIN 202496

#define ZST 136
#define EPD 264

__device__ float g_b2[KCODES];
__device__ int   g_counts[KCODES];
__device__ float g_sse;

// ---- packed fp32x2 (FMA pipe) ----
__device__ __forceinline__ unsigned long long pk2(float x) {
    unsigned long long r; asm("mov.b64 %0, {%1, %1};" : "=l"(r) : "f"(x)); return r;
}
__device__ __forceinline__ void fma2(unsigned long long& d,
                                     unsigned long long a, unsigned long long b) {
    asm("fma.rn.f32x2 %0, %1, %2, %0;" : "+l"(d) : "l"(a), "l"(b));
}
__device__ __forceinline__ void upk(unsigned long long v, float& lo, float& hi) {
    asm("mov.b64 {%0, %1}, %2;" : "=f"(lo), "=f"(hi) : "l"(v));
}
// ---- tf32 MMA (tensor pipe) ----
__device__ __forceinline__ uint32_t to_tf32(float f) {
    uint32_t r; asm("cvt.rna.tf32.f32 %0, %1;" : "=r"(r) : "f"(f)); return r;
}
__device__ __forceinline__ void mma_tf32(float* c, const uint32_t* a, const uint32_t* b) {
    asm volatile(
        "mma.sync.aligned.m16n8k8.row.col.f32.tf32.tf32.f32 "
        "{%0,%1,%2,%3}, {%4,%5,%6,%7}, {%8,%9}, {%0,%1,%2,%3};"
        : "+f"(c[0]), "+f"(c[1]), "+f"(c[2]), "+f"(c[3])
        : "r"(a[0]), "r"(a[1]), "r"(a[2]), "r"(a[3]), "r"(b[0]), "r"(b[1]));
}
__device__ __forceinline__ bool better(float v1, int k1, float v2, int k2) {
    return v1 < v2 || (v1 == v2 && k1 < k2);
}

// ---------------------------------------------------------------------------
// prep: b_k strict sequential + zero accumulators
// ---------------------------------------------------------------------------
__global__ void prep_e_kernel(const float* __restrict__ emb) {
    __shared__ float sb[32 * 257];
    const int tid = threadIdx.x;
    const int k0 = blockIdx.x * 32;
    const float4* src = (const float4*)(emb + (size_t)k0 * CDIM);
    for (int i = tid; i < 2048; i += 256) {
        float4 v = src[i];
        int r = i >> 6, c = (i & 63) * 4;
        float* d = &sb[r * 257 + c];
        d[0]=v.x; d[1]=v.y; d[2]=v.z; d[3]=v.w;
    }
    __syncthreads();
    if (tid < 32) {
        const float* e = &sb[tid * 257];
        float s = 0.f;
        for (int c = 0; c < CDIM; c++) s = __fadd_rn(s, __fmul_rn(e[c], e[c]));
        g_b2[k0 + tid] = s;
        g_counts[k0 + tid] = 0;
    }
    if (blockIdx.x == 0 && tid == 32) g_sse = 0.f;
}

// ---------------------------------------------------------------------------
// main: hybrid FMA(fp32) + tensor(tf32) distance GEMM + argmin + epilogue
// ---------------------------------------------------------------------------
__global__ __launch_bounds__(512, 1)
void vq_main_kernel(const float* __restrict__ z, const float* __restrict__ emb,
                    float* __restrict__ out, int writeIdx) {
    extern __shared__ char sm[];
    float* b2s  = (float*)(sm + SO_B2S);
    float* aRow = (float*)(sm + SO_AROW);
    int*   sIdx = (int*)(sm + SO_SIDX);
    float* red  = (float*)(sm + SO_RED);
    float* rv   = (float*)(sm + SO_RV);
    int*   rk   = (int*)(sm + SO_RK);
    float* cv   = (float*)(sm + SO_CV);
    int*   ck   = (int*)(sm + SO_CK);
    float* dres = (float*)(sm + SO_DRES);
    float* Zs   = (float*)(sm + SO_ZS);
    float* Ebuf = (float*)(sm + SO_EBUF);

    const int tid = threadIdx.x, wid = tid >> 5, lane = tid & 31;
    const int n0 = blockIdx.x * BLK_M;
    const int b = n0 >> 12, s0 = n0 & (SPB - 1);
    const float* zb = z + (size_t)b * (CDIM * SPB) + s0;

    for (int i = tid; i < KCODES; i += 512) b2s[i] = g_b2[i];

    // ---- stage Zs: all 128 rows fp32, [c][m] stride 136, coalesced ----
    for (int i = tid; i < 8192; i += 512) {
        int c = i >> 5, m4 = (i & 31) * 4;
        float4 v = *(const float4*)(zb + (size_t)c * SPB + m4);
        float* d = &Zs[c * ZST + m4];
        d[0]=v.x; d[1]=v.y; d[2]=v.z; d[3]=v.w;
    }
    __syncthreads();

    // ---- strict row sums for all 128 rows ----
    if (tid < BLK_M) {
        float s = 0.f;
        for (int c = 0; c < CDIM; c++) {
            float v = Zs[c * ZST + tid];
            s = __fadd_rn(s, __fmul_rn(v, v));
        }
        aRow[tid] = s;
    }
    __syncthreads();

    const bool isF = wid < 8;
    const int tx = tid & 15, ty = (tid >> 4) & 15;     // FMA-role coords
    const int tw = wid - 8, gq = lane >> 2, tq = lane & 3;  // tensor-role coords

    float av[5]; float bestv[5]; int bestk[5];
    float tv[6][3]; int tk[6][3];
    if (isF) {
#pragma unroll
        for (int r = 0; r < 5; r++) {
            av[r] = (r < 4) ? aRow[ty * 4 + r] : aRow[64 + ty];
            bestv[r] = 3.4e38f; bestk[r] = KCODES;
        }
    } else {
#pragma unroll
        for (int s = 0; s < 6; s++)
#pragma unroll
            for (int i = 0; i < 3; i++) { tv[s][i] = 3.4e38f; tk[s][i] = KCODES; }
    }

    // staging regs: thread stages 16 floats per chunk
    float er[16];
    {   // prefetch (kt0, ch0)
#pragma unroll
        for (int j = 0; j < 4; j++) {
            int lin = tid + 512 * j;
            int code = lin & 255, grp = lin >> 8;
            float4 v = *(const float4*)(emb + (size_t)code * CDIM + grp * 4);
            er[j*4+0]=v.x; er[j*4+1]=v.y; er[j*4+2]=v.z; er[j*4+3]=v.w;
        }
    }

    for (int kt = 0; kt < 4; kt++) {
        const int ktb = kt * 256;
        unsigned long long acc2[5][8];
        float acc[3][4][4];
        if (isF) {
#pragma unroll
            for (int r = 0; r < 5; r++)
#pragma unroll
                for (int g = 0; g < 8; g++) acc2[r][g] = 0ull;
        } else {
#pragma unroll
            for (int ms = 0; ms < 3; ms++)
#pragma unroll
                for (int nt = 0; nt < 4; nt++)
#pragma unroll
                    for (int j = 0; j < 4; j++) acc[ms][nt][j] = 0.f;
        }

        for (int ch = 0; ch < 8; ch++) {
            __syncthreads();                      // Ebuf free
#pragma unroll
            for (int j = 0; j < 4; j++) {
                int lin = tid + 512 * j;
                int code = lin & 255, grp = lin >> 8;
#pragma unroll
                for (int q = 0; q < 4; q++)
                    Ebuf[(grp * 4 + q) * EPD + code] = er[j*4+q];
            }
            __syncthreads();                      // Ebuf ready
            int nxt = kt * 8 + ch + 1;
            if (nxt < 32) {
                int nkt = nxt >> 3, nch = nxt & 7;
#pragma unroll
                for (int j = 0; j < 4; j++) {
                    int lin = tid + 512 * j;
                    int code = lin & 255, grp = lin >> 8;
                    float4 v = *(const float4*)(emb + (size_t)(nkt*256 + code) * CDIM + nch*32 + grp*4);
                    er[j*4+0]=v.x; er[j*4+1]=v.y; er[j*4+2]=v.z; er[j*4+3]=v.w;
                }
            }

            if (isF) {
#pragma unroll 2
                for (int cc = 0; cc < 32; cc++) {
                    const float* zr = &Zs[(ch * 32 + cc) * ZST];
                    float4 z4 = *(const float4*)(zr + ty * 4);
                    float z5 = zr[64 + ty];
                    unsigned long long zp[5] = { pk2(z4.x), pk2(z4.y), pk2(z4.z), pk2(z4.w), pk2(z5) };
#pragma unroll
                    for (int g = 0; g < 4; g++) {
                        ulonglong2 e2 = *(const ulonglong2*)&Ebuf[cc * EPD + g * 64 + tx * 4];
#pragma unroll
                        for (int r = 0; r < 5; r++) {
                            fma2(acc2[r][g*2],   zp[r], e2.x);
                            fma2(acc2[r][g*2+1], zp[r], e2.y);
                        }
                    }
                }
            } else {
#pragma unroll
                for (int ks = 0; ks < 4; ks++) {
                    const int kc = ch * 32 + ks * 8;
                    uint32_t a[3][4];
#pragma unroll
                    for (int ms = 0; ms < 3; ms++) {
                        int rb = 80 + ms * 16 + gq;
                        a[ms][0] = to_tf32(Zs[(kc + tq) * ZST + rb]);
                        a[ms][1] = to_tf32(Zs[(kc + tq) * ZST + rb + 8]);
                        a[ms][2] = to_tf32(Zs[(kc + tq + 4) * ZST + rb]);
                        a[ms][3] = to_tf32(Zs[(kc + tq + 4) * ZST + rb + 8]);
                    }
#pragma unroll
                    for (int nt = 0; nt < 4; nt++) {
                        int nb = tw * 32 + nt * 8 + gq;
                        uint32_t bf[2];
                        bf[0] = to_tf32(Ebuf[(ks * 8 + tq) * EPD + nb]);
                        bf[1] = to_tf32(Ebuf[(ks * 8 + tq + 4) * EPD + nb]);
#pragma unroll
                        for (int ms = 0; ms < 3; ms++)
                            mma_tf32(acc[ms][nt], a[ms], bf);
                    }
                }
            }
        }

        // ---- fold this ktile ----
        if (isF) {
#pragma unroll
            for (int r = 0; r < 5; r++) {
#pragma unroll
                for (int g = 0; g < 4; g++) {
#pragma unroll
                    for (int p = 0; p < 2; p++) {
                        float lo, hi; upk(acc2[r][g*2+p], lo, hi);
                        int k0 = ktb + g * 64 + tx * 4 + 2 * p;
                        float t0 = __fadd_rn(av[r], b2s[k0]);
                        float d0 = __fsub_rn(t0, __fadd_rn(lo, lo));
                        if (d0 < bestv[r]) { bestv[r] = d0; bestk[r] = k0; }
                        float t1 = __fadd_rn(av[r], b2s[k0 + 1]);
                        float d1 = __fsub_rn(t1, __fadd_rn(hi, hi));
                        if (d1 < bestv[r]) { bestv[r] = d1; bestk[r] = k0 + 1; }
                    }
                }
            }
        } else {
#pragma unroll
            for (int ms = 0; ms < 3; ms++)
#pragma unroll
                for (int nt = 0; nt < 4; nt++)
#pragma unroll
                    for (int j = 0; j < 4; j++) {
                        int code = ktb + tw * 32 + nt * 8 + tq * 2 + (j & 1);
                        int s = ms * 2 + (j >> 1);
                        float t = fmaf(-2.f, acc[ms][nt][j], b2s[code]);
                        if (t < tv[s][0]) {
                            tv[s][2]=tv[s][1]; tk[s][2]=tk[s][1];
                            tv[s][1]=tv[s][0]; tk[s][1]=tk[s][0];
                            tv[s][0]=t; tk[s][0]=code;
                        } else if (t < tv[s][1]) {
                            tv[s][2]=tv[s][1]; tk[s][2]=tk[s][1];
                            tv[s][1]=t; tk[s][1]=code;
                        } else if (t < tv[s][2]) {
                            tv[s][2]=t; tk[s][2]=code;
                        }
                    }
        }
    }

    // ---- publish per-group results ----
    if (isF) {
#pragma unroll
        for (int r = 0; r < 5; r++) {
            int m = (r < 4) ? (ty * 4 + r) : (64 + ty);
            rv[m * 16 + tx] = bestv[r];
            rk[m * 16 + tx] = bestk[r];
        }
    } else {
        // merge top-3 across the quad (tq direction)
#pragma unroll
        for (int s = 0; s < 6; s++) {
#pragma unroll
            for (int off = 1; off <= 2; off <<= 1) {
                float b0 = __shfl_xor_sync(0xffffffffu, tv[s][0], off);
                float b1 = __shfl_xor_sync(0xffffffffu, tv[s][1], off);
                float b2v= __shfl_xor_sync(0xffffffffu, tv[s][2], off);
                int   c0 = __shfl_xor_sync(0xffffffffu, tk[s][0], off);
                int   c1 = __shfl_xor_sync(0xffffffffu, tk[s][1], off);
                int   c2 = __shfl_xor_sync(0xffffffffu, tk[s][2], off);
                float a0 = tv[s][0], a1 = tv[s][1], a2 = tv[s][2];
                int   x0 = tk[s][0], x1 = tk[s][1], x2 = tk[s][2];
                float o0,o1,o2; int p0,p1,p2;
                if (better(a0,x0,b0,c0)) {
                    o0=a0; p0=x0;
                    if (better(a1,x1,b0,c0)) { o1=a1; p1=x1;
                        if (better(a2,x2,b0,c0)) { o2=a2; p2=x2; } else { o2=b0; p2=c0; }
                    } else { o1=b0; p1=c0;
                        if (better(a1,x1,b1,c1)) { o2=a1; p2=x1; } else { o2=b1; p2=c1; }
                    }
                } else {
                    o0=b0; p0=c0;
                    if (better(a0,x0,b1,c1)) { o1=a0; p1=x0;
                        if (better(a1,x1,b1,c1)) { o2=a1; p2=x1; } else { o2=b1; p2=c1; }
                    } else { o1=b1; p1=c1;
                        if (better(a0,x0,b2v,c2)) { o2=a0; p2=x0; } else { o2=b2v; p2=c2; }
                    }
                }
                tv[s][0]=o0; tv[s][1]=o1; tv[s][2]=o2;
                tk[s][0]=p0; tk[s][1]=p1; tk[s][2]=p2;
            }
            if (tq == 0) {
                int row48 = (s >> 1) * 16 + gq + (s & 1) * 8;
                int base = (row48 * 8 + tw) * 3;
                cv[base]=tv[s][0]; cv[base+1]=tv[s][1]; cv[base+2]=tv[s][2];
                ck[base]=tk[s][0]; ck[base+1]=tk[s][1]; ck[base+2]=tk[s][2];
            }
        }
    }
    __syncthreads();

    // ---- FMA rows: cross-tx argmin reduce ----
    if (tid < ROWS_F) {
        float bv = 3.4e38f; int bk = KCODES;
        for (int i = 0; i < 16; i++) {
            float v = rv[tid * 16 + i]; int k = rk[tid * 16 + i];
            if (better(v, k, bv, bk)) { bv = v; bk = k; }
        }
        sIdx[tid] = bk;
    }
    // ---- tensor rows: exact recheck of 24 candidates ----
    for (int rr = 0; rr < 3; rr++) {
        int idx = tid + 512 * rr;
        if (idx < ROWS_T * 24) {
            int row48 = idx / 24;
            int row = 80 + row48;
            int k = ck[idx];
            const float* e = emb + (size_t)k * CDIM;
            float p = 0.f;
            for (int c = 0; c < CDIM; c++)
                p = fmaf(Zs[c * ZST + row], e[c], p);
            dres[idx] = __fsub_rn(__fadd_rn(aRow[row], b2s[k]), __fadd_rn(p, p));
        }
    }
    __syncthreads();
    if (tid < ROWS_T) {
        float bv = 3.4e38f; int bk = KCODES;
        for (int c24 = 0; c24 < 24; c24++) {
            int idx = tid * 24 + c24;
            int k = ck[idx]; float d = dres[idx];
            if (better(d, k, bv, bk)) { bv = d; bk = k; }
        }
        sIdx[80 + tid] = bk;
    }
    __syncthreads();
    if (tid < BLK_M) {
        atomicAdd(&g_counts[sIdx[tid]], 1);
        if (writeIdx) out[(size_t)ZQ_ELEMS + 2 + n0 + tid] = (float)sIdx[tid];
    }

    // ---- z_q gather + straight-through + SSE (512 threads) ----
    float* Eb2 = Ebuf;                 // reuse (32 c)x(132 m)
    float lsse = 0.f;
    float* zqout = out + (size_t)b * (CDIM * SPB) + s0;
    for (int p = 0; p < 8; p++) {
        __syncthreads();
#pragma unroll
        for (int r = 0; r < 8; r++) {
            int m = wid * 8 + r;
            Eb2[lane * 132 + m] = emb[(size_t)sIdx[m] * CDIM + p * 32 + lane];
        }
        __syncthreads();
#pragma unroll
        for (int j = 0; j < 8; j++) {
            int id = tid + 512 * j;
            int cc = id >> 7, m = id & 127;
            float v = Eb2[cc * 132 + m];
            int c = p * 32 + cc;
            float zv = Zs[c * ZST + m];
            float diff = __fsub_rn(v, zv);
            lsse = fmaf(diff, diff, lsse);
            zqout[(size_t)c * SPB + m] = __fadd_rn(zv, diff);
        }
    }
#pragma unroll
    for (int o = 16; o > 0; o >>= 1) lsse += __shfl_xor_sync(0xffffffffu, lsse, o);
    if (lane == 0) red[wid] = lsse;
    __syncthreads();
    if (tid == 0) {
        float s = 0.f;
        for (int i = 0; i < 16; i++) s += red[i];
        atomicAdd(&g_sse, s);
    }
}

// ---------------------------------------------------------------------------
__global__ void finalize_kernel(float* __restrict__ out) {
    __shared__ float red[32];
    int t = threadIdx.x;
    float c = (float)g_counts[t];
    float e = c * (1.0f / 32768.0f);
    float h = e * logf(e + 1e-10f);
#pragma unroll
    for (int o = 16; o > 0; o >>= 1) h += __shfl_xor_sync(0xffffffffu, h, o);
    if ((t & 31) == 0) red[t >> 5] = h;
    __syncthreads();
    if (t < 32) {
        float v = red[t];
#pragma unroll
        for (int o = 16; o > 0; o >>= 1) v += __shfl_xor_sync(0xffffffffu, v, o);
        if (t == 0) {
            out[ZQ_ELEMS]     = 1.25f * g_sse * (1.0f / 8388608.0f);
            out[ZQ_ELEMS + 1] = expf(-v);
        }
    }
}

// ---------------------------------------------------------------------------
extern "C" void kernel_launch(void* const* d_in, const int* in_sizes, int n_in,
                              void* d_out, int out_size) {
    const float* z   = (const float*)d_in[0];
    const float* emb = (const float*)d_in[1];
    if (n_in >= 2 && in_sizes[0] == KCODES * CDIM && in_sizes[1] == ZQ_ELEMS) {
        z = (const float*)d_in[1]; emb = (const float*)d_in[0];
    }
    float* out = (float*)d_out;
    int writeScalars = out_size >= ZQ_ELEMS + 2;
    int writeIdx     = out_size >= ZQ_ELEMS + 2 + NROWS;

    cudaFuncSetAttribute(vq_main_kernel, cudaFuncAttributeMaxDynamicSharedMemorySize, SMEM_MAIN);

    prep_e_kernel<<<32, 256>>>(emb);
    vq_main_kernel<<<NROWS / BLK_M, 512, SMEM_MAIN>>>(z, emb, out, writeIdx);
    if (writeScalars) finalize_kernel<<<1, 1024>>>(out);
}

// round 11
// speedup vs baseline: 2.5868x; 2.5868x over previous
#include <cuda_runtime.h>
#include <math.h>

#define NROWS     32768
#define CDIM      256
#define KCODES    1024
#define BLK_M     128
#define SPB       4096          // spatial positions per batch element (16*16*16)
#define ZQ_ELEMS  8388608       // 8*256*4096
#define EPAD      132           // padded row stride for E-tile in smem
#define EBUF_OFF  32768         // Zs = 256*128 floats
#define EBUF_HALF 4224          // one E buffer = 32*132 floats
// Zs + 2xEbuf + sIdx + aRow + b2s + red
#define SMEM_FLOATS (32768 + 2*4224 + 128 + 128 + 1024 + 8)

__device__ float g_b2[KCODES];      // sum e_k^2, strict sequential rounding
__device__ int   g_counts[KCODES];
__device__ float g_sse;
__device__ int   g_done;

// ---- packed fp32x2 helpers (Blackwell dual-rate fp32 pipe) --------------
__device__ __forceinline__ unsigned long long pk2(float x) {
    unsigned long long r;
    asm("mov.b64 %0, {%1, %1};" : "=l"(r) : "f"(x));
    return r;
}
__device__ __forceinline__ void fma2(unsigned long long& d,
                                     unsigned long long a, unsigned long long b) {
    asm("fma.rn.f32x2 %0, %1, %2, %0;" : "+l"(d) : "l"(a), "l"(b));
}
__device__ __forceinline__ void upk(unsigned long long v, float& lo, float& hi) {
    asm("mov.b64 {%0, %1}, %2;" : "=f"(lo), "=f"(hi) : "l"(v));
}

// ---------------------------------------------------------------------------
// Kernel 1: b_k = sum_c fl(fl(e^2)+...) sequential ascending c (strict, no fma)
// 64 blocks x 256 threads, 16 codes per block.
// ---------------------------------------------------------------------------
__global__ void bias_kernel(const float* __restrict__ emb) {
    __shared__ float sb[16 * 257];
    const int tid = threadIdx.x;
    const int k0 = blockIdx.x * 16;
    const float4* src = (const float4*)(emb + (size_t)k0 * CDIM);
    for (int i = tid; i < 1024; i += 256) {       // 16 rows x 64 float4
        float4 v = src[i];
        int r = i >> 6, c = (i & 63) * 4;
        float* d = &sb[r * 257 + c];
        d[0]=v.x; d[1]=v.y; d[2]=v.z; d[3]=v.w;
    }
    __syncthreads();
    if (tid < 16) {
        const float* e = &sb[tid * 257];
        float s = 0.f;
        for (int c = 0; c < CDIM; c++)
            s = __fadd_rn(s, __fmul_rn(e[c], e[c]));
        g_b2[k0 + tid] = s;
        g_counts[k0 + tid] = 0;
    }
    if (blockIdx.x == 0 && tid == 16) g_sse = 0.f;
}

// ---------------------------------------------------------------------------
// Kernel 2: main — distance GEMM (FFMA2) + argmin + gather z_q + SSE + counts
//           + fused finalize in the last-finishing block
// ---------------------------------------------------------------------------
__global__ __launch_bounds__(256, 1)
void vq_main_kernel(const float* __restrict__ z, const float* __restrict__ emb,
                    float* __restrict__ out, int writeIdx, int writeScalars) {
    extern __shared__ float sm[];
    float* Zs   = sm;                             // [256 c][128 m]
    float* Ebuf = sm + EBUF_OFF;                  // 2 x [32 cc][132]
    int*   sIdx = (int*)(sm + EBUF_OFF + 2 * EBUF_HALF);
    float* aRow = sm + EBUF_OFF + 2 * EBUF_HALF + 128;
    float* b2s  = sm + EBUF_OFF + 2 * EBUF_HALF + 256;
    float* red  = sm + EBUF_OFF + 2 * EBUF_HALF + 256 + 1024;

    const int tid = threadIdx.x;
    const int tx = tid & 15, ty = tid >> 4;
    const int n0 = blockIdx.x * BLK_M;
    const int b  = n0 >> 12;
    const int s0 = n0 & (SPB - 1);
    const float* zb = z + (size_t)b * (CDIM * SPB) + s0;

    // ---- stage b2 into smem (coalesced) ----
    for (int i = tid; i < KCODES; i += 256) b2s[i] = g_b2[i];

    // ---- load Z tile into smem (transposed to [c][m]), coalesced ----
    {
        int lane4 = (tid & 31) * 4;
        for (int c = tid >> 5; c < CDIM; c += 8) {
            float4 v = *(const float4*)(zb + (size_t)c * SPB + lane4);
            *(float4*)&Zs[c * BLK_M + lane4] = v;
        }
    }
    __syncthreads();

    // ---- a_m = sum_c fl(fl(z^2)+...) sequential ascending c (strict) ----
    if (tid < BLK_M) {
        float s = 0.f;
        for (int c = 0; c < CDIM; c++) {
            float v = Zs[c * BLK_M + tid];
            s = __fadd_rn(s, __fmul_rn(v, v));
        }
        aRow[tid] = s;
    }
    __syncthreads();

    float av[8];
#pragma unroll
    for (int i = 0; i < 8; i++) {
        int m = (i < 4) ? (ty * 4 + i) : (64 + ty * 4 + i - 4);
        av[i] = aRow[m];
    }

    float bestv[8];
    int   bestk[8];
#pragma unroll
    for (int i = 0; i < 8; i++) { bestv[i] = 3.4e38f; bestk[i] = 0; }

    const int cc0 = tid & 31, kk0 = tid >> 5;
    float er[16];
    {   // prefetch E chunk (ktile 0, cchunk 0)
        const float* ep = emb + (size_t)kk0 * CDIM + cc0;
#pragma unroll
        for (int i = 0; i < 16; i++) er[i] = ep[(size_t)(8 * i) * CDIM];
    }

    for (int kt = 0; kt < 8; kt++) {
        unsigned long long acc2[4][8];   // (row pair) x (8 k-cols), packed fp32x2
#pragma unroll
        for (int p = 0; p < 4; p++)
#pragma unroll
            for (int j = 0; j < 8; j++) acc2[p][j] = 0ull;

        for (int ch = 0; ch < 8; ch++) {
            const int gch = kt * 8 + ch;
            float* cur = Ebuf + (gch & 1) * EBUF_HALF;
            // stage this chunk into its parity buffer (safe: peers read other parity;
            // same-parity reuse is separated by the barrier below of the previous chunk)
#pragma unroll
            for (int i = 0; i < 16; i++) cur[cc0 * EPAD + kk0 + 8 * i] = er[i];
            __syncthreads();
            int nch = ch + 1, nkt = kt;
            if (nch == 8) { nch = 0; nkt++; }
            if (nkt < 8) {
                const float* ep = emb + (size_t)(nkt * 128 + kk0) * CDIM + nch * 32 + cc0;
#pragma unroll
                for (int i = 0; i < 16; i++) er[i] = ep[(size_t)(8 * i) * CDIM];
            }
            const int cbase = ch * 32;
#pragma unroll 8
            for (int cc = 0; cc < 32; cc++) {
                const float* zrow = &Zs[(cbase + cc) * BLK_M];
                ulonglong2 z0 = *(const ulonglong2*)(zrow + ty * 4);        // rows i0..i3
                ulonglong2 z1 = *(const ulonglong2*)(zrow + 64 + ty * 4);   // rows i4..i7
                float4 e0 = *(const float4*)&cur[cc * EPAD + tx * 4];
                float4 e1 = *(const float4*)&cur[cc * EPAD + 64 + tx * 4];
                unsigned long long eb2[8] = {
                    pk2(e0.x), pk2(e0.y), pk2(e0.z), pk2(e0.w),
                    pk2(e1.x), pk2(e1.y), pk2(e1.z), pk2(e1.w)};
#pragma unroll
                for (int j = 0; j < 8; j++) {
                    fma2(acc2[0][j], z0.x, eb2[j]);
                    fma2(acc2[1][j], z0.y, eb2[j]);
                    fma2(acc2[2][j], z1.x, eb2[j]);
                    fma2(acc2[3][j], z1.y, eb2[j]);
                }
            }
        }
        // ---- unpack + fold: d = fl(fl(a+b_k) - fl(2*dot)), argmin ----
        const int k0 = kt * 128;
        float bj[8];
#pragma unroll
        for (int j = 0; j < 8; j++) {
            int kl = (j < 4) ? (tx * 4 + j) : (64 + tx * 4 + j - 4);
            bj[j] = b2s[k0 + kl];
        }
#pragma unroll
        for (int p = 0; p < 4; p++) {
#pragma unroll
            for (int j = 0; j < 8; j++) {
                float dlo, dhi;
                upk(acc2[p][j], dlo, dhi);
                int i0 = 2 * p, i1 = 2 * p + 1;
                int kl = (j < 4) ? (tx * 4 + j) : (64 + tx * 4 + j - 4);
                float t0 = __fadd_rn(av[i0], bj[j]);
                float d0 = __fsub_rn(t0, __fadd_rn(dlo, dlo));
                if (d0 < bestv[i0]) { bestv[i0] = d0; bestk[i0] = k0 + kl; }
                float t1 = __fadd_rn(av[i1], bj[j]);
                float d1 = __fsub_rn(t1, __fadd_rn(dhi, dhi));
                if (d1 < bestv[i1]) { bestv[i1] = d1; bestk[i1] = k0 + kl; }
            }
        }
    }

    // ---- reduce argmin across the 16 tx threads of each row ----
    float* rv = Ebuf;
    int*   rk = (int*)(Ebuf + 2048);
    __syncthreads();
#pragma unroll
    for (int i = 0; i < 8; i++) {
        int m = (i < 4) ? (ty * 4 + i) : (64 + ty * 4 + i - 4);
        rv[m * 16 + tx] = bestv[i];
        rk[m * 16 + tx] = bestk[i];
    }
    __syncthreads();
    if (tid < BLK_M) {
        int m = tid;
        float bv = 3.4e38f; int bk = KCODES;
        for (int i = 0; i < 16; i++) {
            float v = rv[m * 16 + i]; int k = rk[m * 16 + i];
            if (v < bv || (v == bv && k < bk)) { bv = v; bk = k; }
        }
        sIdx[m] = bk;
        atomicAdd(&g_counts[bk], 1);
        if (writeIdx) out[(size_t)ZQ_ELEMS + 2 + n0 + m] = (float)bk;
    }
    __syncthreads();

    // ---- z_q gather + straight-through fl(z + fl(e - z)) + SSE ----
    const int w = tid >> 5, lane = tid & 31;
    float lsse = 0.f;
    float* zqout = out + (size_t)b * (CDIM * SPB) + s0;
    for (int p = 0; p < 8; p++) {
        float* gbuf = Ebuf + (p & 1) * EBUF_HALF;
#pragma unroll
        for (int r = 0; r < 16; r++) {
            int m = w * 16 + r;
            gbuf[lane * EPAD + m] = emb[(size_t)sIdx[m] * CDIM + p * 32 + lane];
        }
        __syncthreads();
#pragma unroll
        for (int j = 0; j < 16; j++) {
            int id = tid + 256 * j;
            int cc = id >> 7, m = id & 127;
            float v  = gbuf[cc * EPAD + m];
            int c = p * 32 + cc;
            float zv = Zs[c * BLK_M + m];
            float diff = __fsub_rn(v, zv);           // z_q - zp, single rounding
            lsse = fmaf(diff, diff, lsse);
            zqout[(size_t)c * SPB + m] = __fadd_rn(zv, diff);  // zp + sg(z_q - zp)
        }
    }
#pragma unroll
    for (int o = 16; o > 0; o >>= 1) lsse += __shfl_xor_sync(0xffffffffu, lsse, o);
    if (lane == 0) red[w] = lsse;
    __syncthreads();
    if (tid == 0) {
        float s = 0.f;
        for (int i = 0; i < 8; i++) s += red[i];
        atomicAdd(&g_sse, s);
    }

    // ---- fused finalize: last-finishing block computes loss + perplexity ----
    if (!writeScalars) return;
    __shared__ int sLast;
    if (tid == 0) {
        __threadfence();
        sLast = (atomicAdd(&g_done, 1) == (int)gridDim.x - 1);
    }
    __syncthreads();
    if (!sLast) return;
    // all other blocks' g_counts/g_sse updates are visible (fence + atomic chain)
    float h = 0.f;
#pragma unroll
    for (int q = 0; q < 4; q++) {
        float c = (float)g_counts[tid + 256 * q];
        float e = c * (1.0f / 32768.0f);
        h += e * logf(e + 1e-10f);
    }
#pragma unroll
    for (int o = 16; o > 0; o >>= 1) h += __shfl_xor_sync(0xffffffffu, h, o);
    if (lane == 0) red[w] = h;
    __syncthreads();
    if (tid == 0) {
        float v = 0.f;
        for (int i = 0; i < 8; i++) v += red[i];
        // LEGACY loss = mse + 0.25*mse = 1.25*mse
        out[ZQ_ELEMS]     = 1.25f * g_sse * (1.0f / 8388608.0f);
        out[ZQ_ELEMS + 1] = expf(-v);
        g_done = 0;                       // reset for deterministic graph replay
    }
}

// ---------------------------------------------------------------------------
extern "C" void kernel_launch(void* const* d_in, const int* in_sizes, int n_in,
                              void* d_out, int out_size) {
    const float* z   = (const float*)d_in[0];
    const float* emb = (const float*)d_in[1];
    if (n_in >= 2 && in_sizes[0] == KCODES * CDIM && in_sizes[1] == ZQ_ELEMS) {
        // defensive: inputs arrived swapped
        z   = (const float*)d_in[1];
        emb = (const float*)d_in[0];
    }
    float* out = (float*)d_out;
    int writeScalars = out_size >= ZQ_ELEMS + 2;
    int writeIdx     = out_size >= ZQ_ELEMS + 2 + NROWS;

    size_t smem = SMEM_FLOATS * sizeof(float);   // 170528 B
    cudaFuncSetAttribute(vq_main_kernel,
                         cudaFuncAttributeMaxDynamicSharedMemorySize, (int)smem);

    bias_kernel<<<64, 256>>>(emb);
    vq_main_kernel<<<NROWS / BLK_M, 256, smem>>>(z, emb, out, writeIdx, writeScalars);
}